// round 1
// baseline (speedup 1.0000x reference)
#include <cuda_runtime.h>

#define PPIX 3136
#define CH 256
#define DIM 32
#define KER 7
#define K2 49
#define TILE 14
#define HALO 20
#define HALOSZ 400
#define ROWP 33

// scratch (allocation-free rule: device globals)
__device__ __align__(16) float g_Qp[2 * PPIX * CH];
__device__ __align__(16) float g_Kp[2 * PPIX * CH];
__device__ __align__(16) float g_Vp[2 * PPIX * CH];
__device__ __align__(16) float g_O [2 * PPIX * CH];
__device__ __align__(16) float g_bck[CH];
__device__ __align__(16) float g_bcv[CH];

// ---------------------------------------------------------------------------
// bconst[c'] = pos * sum_c W[c'][c] + b[c']  for the K and V blocks of in_proj
// ---------------------------------------------------------------------------
__global__ void bconst_kernel(const float* __restrict__ W, const float* __restrict__ b,
                              const float* __restrict__ pos) {
    int c = threadIdx.x;
    float p = pos[0];
    const float* wk = W + (CH + c) * CH;
    const float* wv = W + (2 * CH + c) * CH;
    float sk = 0.f, sv = 0.f;
    #pragma unroll 8
    for (int j = 0; j < CH; j++) { sk += wk[j]; sv += wv[j]; }
    g_bck[c] = p * sk + b[CH + c];
    g_bcv[c] = p * sv + b[2 * CH + c];
}

// ---------------------------------------------------------------------------
// Projection GEMM: Out[p][c'] = sum_c W[c'][c] * In[c][p]  (+ bias for Q only)
// In is channel-major (C,P).  128x128 tile, K-step 8, 8x8 per thread.
// blockIdx.z = proj*2 + n  (proj: 0=Q from queries, 1=K, 2=V from key)
// ---------------------------------------------------------------------------
__global__ void proj_gemm(const float* __restrict__ queries, const float* __restrict__ key,
                          const float* __restrict__ Wall, const float* __restrict__ bvec) {
    int proj = blockIdx.z >> 1;
    int n    = blockIdx.z & 1;
    const float* In = ((proj == 0) ? queries : key) + (size_t)n * CH * PPIX;
    const float* W  = Wall + (size_t)proj * CH * CH;
    float* Out = (proj == 0 ? g_Qp : (proj == 1 ? g_Kp : g_Vp)) + (size_t)n * PPIX * CH;

    __shared__ float As[8][128];
    __shared__ float Bs[8][132];

    int tid = threadIdx.x;
    int m0 = blockIdx.x * 128;
    int c0 = blockIdx.y * 128;
    int ty = tid >> 4, tx = tid & 15;

    float acc[8][8];
    #pragma unroll
    for (int i = 0; i < 8; i++)
        #pragma unroll
        for (int j = 0; j < 8; j++) acc[i][j] = 0.f;

    int la_k = tid >> 5;            // 0..7
    int la_m = (tid & 31) << 2;     // 0..124 step 4
    int lb_c = tid >> 1;            // 0..127
    int lb_k = (tid & 1) << 2;      // 0 or 4

    for (int kt = 0; kt < CH; kt += 8) {
        float4 va = make_float4(0.f, 0.f, 0.f, 0.f);
        if (m0 + la_m < PPIX)
            va = *reinterpret_cast<const float4*>(In + (size_t)(kt + la_k) * PPIX + m0 + la_m);
        *reinterpret_cast<float4*>(&As[la_k][la_m]) = va;

        float4 vb = *reinterpret_cast<const float4*>(W + (size_t)(c0 + lb_c) * CH + kt + lb_k);
        Bs[lb_k + 0][lb_c] = vb.x;
        Bs[lb_k + 1][lb_c] = vb.y;
        Bs[lb_k + 2][lb_c] = vb.z;
        Bs[lb_k + 3][lb_c] = vb.w;
        __syncthreads();

        #pragma unroll
        for (int k = 0; k < 8; k++) {
            float a[8], bb[8];
            *reinterpret_cast<float4*>(a)     = *reinterpret_cast<const float4*>(&As[k][ty * 8]);
            *reinterpret_cast<float4*>(a + 4) = *reinterpret_cast<const float4*>(&As[k][ty * 8 + 4]);
            *reinterpret_cast<float4*>(bb)     = *reinterpret_cast<const float4*>(&Bs[k][tx * 8]);
            *reinterpret_cast<float4*>(bb + 4) = *reinterpret_cast<const float4*>(&Bs[k][tx * 8 + 4]);
            #pragma unroll
            for (int i = 0; i < 8; i++)
                #pragma unroll
                for (int j = 0; j < 8; j++)
                    acc[i][j] += a[i] * bb[j];
        }
        __syncthreads();
    }

    #pragma unroll
    for (int j = 0; j < 8; j++) {
        int cc = c0 + tx * 8 + j;
        float bias = (proj == 0) ? bvec[cc] : 0.f;
        #pragma unroll
        for (int i = 0; i < 8; i++) {
            int m = m0 + ty * 8 + i;
            if (m < PPIX) Out[(size_t)m * CH + cc] = acc[i][j] + bias;
        }
    }
}

// ---------------------------------------------------------------------------
// Local attention: one block = 14x14 pixel tile, one (n, head).
// Halo 20x20 of K,V (+bconst) staged in smem; zero-pad neighbors = bconst only.
// ---------------------------------------------------------------------------
__global__ void attn_kernel() {
    extern __shared__ float sm[];
    float* Ks = sm;                     // HALOSZ * ROWP
    float* Vs = sm + HALOSZ * ROWP;

    int tx0 = blockIdx.x * TILE;
    int ty0 = blockIdx.y * TILE;
    int h = blockIdx.z & 7;
    int n = blockIdx.z >> 3;
    int tid = threadIdx.x;
    int cbase = h * DIM;

    const float* Kp = g_Kp + (size_t)n * PPIX * CH;
    const float* Vp = g_Vp + (size_t)n * PPIX * CH;

    for (int idx = tid; idx < HALOSZ * DIM; idx += blockDim.x) {
        int hp = idx >> 5;
        int hc = idx & 31;
        int gy = ty0 - 3 + hp / HALO;
        int gx = tx0 - 3 + hp % HALO;
        float kval = g_bck[cbase + hc];
        float vval = g_bcv[cbase + hc];
        if (gy >= 0 && gy < 56 && gx >= 0 && gx < 56) {
            size_t gp = (size_t)(gy * 56 + gx) * CH + cbase + hc;
            kval += Kp[gp];
            vval += Vp[gp];
        }
        Ks[hp * ROWP + hc] = kval;
        Vs[hp * ROWP + hc] = vval;
    }
    __syncthreads();

    if (tid >= TILE * TILE) return;
    int ly = tid / TILE, lx = tid % TILE;
    int p = (ty0 + ly) * 56 + (tx0 + lx);

    float q[DIM];
    const float* qptr = g_Qp + (size_t)n * PPIX * CH + (size_t)p * CH + cbase;
    #pragma unroll
    for (int i = 0; i < 8; i++)
        *reinterpret_cast<float4*>(q + i * 4) = *reinterpret_cast<const float4*>(qptr + i * 4);

    const float scale = 0.17677669529663687f;   // 1/sqrt(32)
    float sc[K2];
    #pragma unroll
    for (int ti = 0; ti < KER; ti++) {
        #pragma unroll
        for (int tj = 0; tj < KER; tj++) {
            const float* kr = Ks + ((ly + ti) * HALO + (lx + tj)) * ROWP;
            float s = 0.f;
            #pragma unroll
            for (int c = 0; c < DIM; c++) s += q[c] * kr[c];
            sc[ti * KER + tj] = s * scale;
        }
    }

    float mx = sc[0];
    #pragma unroll
    for (int t = 1; t < K2; t++) mx = fmaxf(mx, sc[t]);
    float sum = 0.f;
    #pragma unroll
    for (int t = 0; t < K2; t++) { sc[t] = __expf(sc[t] - mx); sum += sc[t]; }
    float inv = 1.f / sum;

    float o[DIM];
    #pragma unroll
    for (int c = 0; c < DIM; c++) o[c] = 0.f;
    #pragma unroll
    for (int ti = 0; ti < KER; ti++) {
        #pragma unroll
        for (int tj = 0; tj < KER; tj++) {
            const float* vr = Vs + ((ly + ti) * HALO + (lx + tj)) * ROWP;
            float w = sc[ti * KER + tj] * inv;
            #pragma unroll
            for (int c = 0; c < DIM; c++) o[c] += w * vr[c];
        }
    }

    float* optr = g_O + (size_t)n * PPIX * CH + (size_t)p * CH + cbase;
    #pragma unroll
    for (int i = 0; i < 8; i++)
        *reinterpret_cast<float4*>(optr + i * 4) = *reinterpret_cast<const float4*>(o + i * 4);
}

// ---------------------------------------------------------------------------
// Out projection: out[n][c'][p] = sum_c O[n][p][c] * Wout[c'][c] + bout[c']
// ---------------------------------------------------------------------------
__global__ void outproj_gemm(const float* __restrict__ Wout, const float* __restrict__ bout,
                             float* __restrict__ out) {
    int n = blockIdx.z;
    const float* A = g_O + (size_t)n * PPIX * CH;

    __shared__ float As[8][128];
    __shared__ float Bs[8][132];

    int tid = threadIdx.x;
    int m0 = blockIdx.x * 128;
    int c0 = blockIdx.y * 128;
    int ty = tid >> 4, tx = tid & 15;

    float acc[8][8];
    #pragma unroll
    for (int i = 0; i < 8; i++)
        #pragma unroll
        for (int j = 0; j < 8; j++) acc[i][j] = 0.f;

    int la_m = tid >> 1;
    int la_k = (tid & 1) << 2;
    int lb_c = tid >> 1;
    int lb_k = (tid & 1) << 2;

    for (int kt = 0; kt < CH; kt += 8) {
        float4 va = make_float4(0.f, 0.f, 0.f, 0.f);
        if (m0 + la_m < PPIX)
            va = *reinterpret_cast<const float4*>(A + (size_t)(m0 + la_m) * CH + kt + la_k);
        As[la_k + 0][la_m] = va.x;
        As[la_k + 1][la_m] = va.y;
        As[la_k + 2][la_m] = va.z;
        As[la_k + 3][la_m] = va.w;

        float4 vb = *reinterpret_cast<const float4*>(Wout + (size_t)(c0 + lb_c) * CH + kt + lb_k);
        Bs[lb_k + 0][lb_c] = vb.x;
        Bs[lb_k + 1][lb_c] = vb.y;
        Bs[lb_k + 2][lb_c] = vb.z;
        Bs[lb_k + 3][lb_c] = vb.w;
        __syncthreads();

        #pragma unroll
        for (int k = 0; k < 8; k++) {
            float a[8], bb[8];
            *reinterpret_cast<float4*>(a)     = *reinterpret_cast<const float4*>(&As[k][ty * 8]);
            *reinterpret_cast<float4*>(a + 4) = *reinterpret_cast<const float4*>(&As[k][ty * 8 + 4]);
            *reinterpret_cast<float4*>(bb)     = *reinterpret_cast<const float4*>(&Bs[k][tx * 8]);
            *reinterpret_cast<float4*>(bb + 4) = *reinterpret_cast<const float4*>(&Bs[k][tx * 8 + 4]);
            #pragma unroll
            for (int i = 0; i < 8; i++)
                #pragma unroll
                for (int j = 0; j < 8; j++)
                    acc[i][j] += a[i] * bb[j];
        }
        __syncthreads();
    }

    #pragma unroll
    for (int j = 0; j < 8; j++) {
        int cc = c0 + tx * 8 + j;
        float bias = bout[cc];
        #pragma unroll
        for (int i = 0; i < 8; i++) {
            int m = m0 + ty * 8 + i;
            if (m < PPIX)
                out[(size_t)n * CH * PPIX + (size_t)cc * PPIX + m] = acc[i][j] + bias;
        }
    }
}

extern "C" void kernel_launch(void* const* d_in, const int* in_sizes, int n_in,
                              void* d_out, int out_size) {
    const float* queries = (const float*)d_in[0];
    const float* key     = (const float*)d_in[1];
    const float* pos     = (const float*)d_in[2];
    const float* ipw     = (const float*)d_in[3];
    const float* ipb     = (const float*)d_in[4];
    const float* opw     = (const float*)d_in[5];
    const float* opb     = (const float*)d_in[6];
    float* out = (float*)d_out;

    bconst_kernel<<<1, 256>>>(ipw, ipb, pos);
    proj_gemm<<<dim3(25, 2, 6), 256>>>(queries, key, ipw, ipb);

    int smem = 2 * HALOSZ * ROWP * (int)sizeof(float);   // 105600 B
    cudaFuncSetAttribute(attn_kernel, cudaFuncAttributeMaxDynamicSharedMemorySize, smem);
    attn_kernel<<<dim3(4, 4, 16), 256, smem>>>();

    outproj_gemm<<<dim3(25, 2, 2), 256>>>(opw, opb, out);
}

// round 2
// speedup vs baseline: 1.5648x; 1.5648x over previous
#include <cuda_runtime.h>
#include <cstdint>

#define PPIX 3136
#define CH 256
#define DIM 32
#define KER 7
#define K2 49
#define TILE 14
#define HALO 20
#define HALOSZ 400
#define ROWP 36

// scratch (allocation-free rule: device globals)
__device__ __align__(16) float g_Qp[2 * PPIX * CH];
__device__ __align__(16) float g_Kp[2 * PPIX * CH];
__device__ __align__(16) float g_Vp[2 * PPIX * CH];
__device__ __align__(16) float g_O [2 * PPIX * CH];
__device__ __align__(16) float g_bck[CH];
__device__ __align__(16) float g_bcv[CH];

// ---------------------------------------------------------------------------
// helpers: tf32 convert + m16n8k8 tensor-core mma
// ---------------------------------------------------------------------------
__device__ __forceinline__ uint32_t f2tf(float x) {
    uint32_t r;
    asm("cvt.rna.tf32.f32 %0, %1;" : "=r"(r) : "f"(x));
    return r;
}

__device__ __forceinline__ void mma_tf32(float c[4], const uint32_t a[4], const uint32_t b[2]) {
    asm volatile(
        "mma.sync.aligned.m16n8k8.row.col.f32.tf32.tf32.f32 "
        "{%0,%1,%2,%3}, {%4,%5,%6,%7}, {%8,%9}, {%0,%1,%2,%3};"
        : "+f"(c[0]), "+f"(c[1]), "+f"(c[2]), "+f"(c[3])
        : "r"(a[0]), "r"(a[1]), "r"(a[2]), "r"(a[3]), "r"(b[0]), "r"(b[1]));
}

// ---------------------------------------------------------------------------
// bconst[c'] = pos * sum_c W[c'][c] + b[c']  for the K and V blocks of in_proj
// ---------------------------------------------------------------------------
__global__ void bconst_kernel(const float* __restrict__ W, const float* __restrict__ b,
                              const float* __restrict__ pos) {
    int c = threadIdx.x;
    float p = pos[0];
    const float* wk = W + (CH + c) * CH;
    const float* wv = W + (2 * CH + c) * CH;
    float sk = 0.f, sv = 0.f;
    #pragma unroll 8
    for (int j = 0; j < CH; j++) { sk += wk[j]; sv += wv[j]; }
    g_bck[c] = p * sk + b[CH + c];
    g_bcv[c] = p * sv + b[2 * CH + c];
}

// ---------------------------------------------------------------------------
// Projection GEMM (tf32 tensor cores):
//   Out[p][c'] = sum_c W[c'][c] * In[c][p]   (+ bias for Q only)
// In is channel-major (C,P).  BM=64 (3136=49*64, no bounds), BN=128, BK=16.
// 8 warps: 2 (m) x 4 (n), warp tile 32x32, mma m16n8k8.
// blockIdx.z = proj*2 + n
// ---------------------------------------------------------------------------
__global__ void proj_gemm(const float* __restrict__ queries, const float* __restrict__ key,
                          const float* __restrict__ Wall, const float* __restrict__ bvec) {
    int proj = blockIdx.z >> 1;
    int n    = blockIdx.z & 1;
    const float* In = ((proj == 0) ? queries : key) + (size_t)n * CH * PPIX;
    const float* W  = Wall + (size_t)proj * CH * CH;
    float* Out = (proj == 0 ? g_Qp : (proj == 1 ? g_Kp : g_Vp)) + (size_t)n * PPIX * CH;

    __shared__ uint32_t As[16][72];    // k-major, pad 8 -> conflict-free frags
    __shared__ uint32_t Bs[16][136];

    int tid = threadIdx.x;
    int m0 = blockIdx.x * 64;
    int c0 = blockIdx.y * 128;
    int w = tid >> 5, lane = tid & 31;
    int r = lane >> 2, tig = lane & 3;
    int wm = (w & 1) * 32;
    int wn = (w >> 1) * 32;

    float acc[2][4][4];
    #pragma unroll
    for (int mt = 0; mt < 2; mt++)
        #pragma unroll
        for (int nt = 0; nt < 4; nt++)
            #pragma unroll
            for (int i = 0; i < 4; i++) acc[mt][nt][i] = 0.f;

    int a_k = tid >> 4;            // 0..15
    int a_m = (tid & 15) * 4;      // 0..60
    int b_n = tid >> 2;            // 0..63
    int b_k = (tid & 3) * 4;       // 0..12

    for (int kt = 0; kt < CH; kt += 16) {
        // A tile: In[k][m] already k-major -> direct vectorized copy
        float4 va = *reinterpret_cast<const float4*>(In + (size_t)(kt + a_k) * PPIX + m0 + a_m);
        As[a_k][a_m + 0] = f2tf(va.x);
        As[a_k][a_m + 1] = f2tf(va.y);
        As[a_k][a_m + 2] = f2tf(va.z);
        As[a_k][a_m + 3] = f2tf(va.w);
        // B tile: W[n][k] row-major -> transpose into k-major smem
        #pragma unroll
        for (int ph = 0; ph < 2; ph++) {
            int nn = ph * 64 + b_n;
            float4 vb = *reinterpret_cast<const float4*>(W + (size_t)(c0 + nn) * CH + kt + b_k);
            Bs[b_k + 0][nn] = f2tf(vb.x);
            Bs[b_k + 1][nn] = f2tf(vb.y);
            Bs[b_k + 2][nn] = f2tf(vb.z);
            Bs[b_k + 3][nn] = f2tf(vb.w);
        }
        __syncthreads();

        #pragma unroll
        for (int ks = 0; ks < 2; ks++) {
            int k0 = ks * 8;
            uint32_t a[2][4], b[4][2];
            #pragma unroll
            for (int mt = 0; mt < 2; mt++) {
                int m = wm + mt * 16 + r;
                a[mt][0] = As[k0 + tig][m];
                a[mt][1] = As[k0 + tig][m + 8];
                a[mt][2] = As[k0 + tig + 4][m];
                a[mt][3] = As[k0 + tig + 4][m + 8];
            }
            #pragma unroll
            for (int nt = 0; nt < 4; nt++) {
                int nn = wn + nt * 8 + r;
                b[nt][0] = Bs[k0 + tig][nn];
                b[nt][1] = Bs[k0 + tig + 4][nn];
            }
            #pragma unroll
            for (int mt = 0; mt < 2; mt++)
                #pragma unroll
                for (int nt = 0; nt < 4; nt++)
                    mma_tf32(acc[mt][nt], a[mt], b[nt]);
        }
        __syncthreads();
    }

    #pragma unroll
    for (int mt = 0; mt < 2; mt++) {
        int row0 = m0 + wm + mt * 16 + r;
        #pragma unroll
        for (int nt = 0; nt < 4; nt++) {
            int cc = c0 + wn + nt * 8 + 2 * tig;
            float b0 = (proj == 0) ? bvec[cc] : 0.f;
            float b1 = (proj == 0) ? bvec[cc + 1] : 0.f;
            *reinterpret_cast<float2*>(Out + (size_t)row0 * CH + cc) =
                make_float2(acc[mt][nt][0] + b0, acc[mt][nt][1] + b1);
            *reinterpret_cast<float2*>(Out + (size_t)(row0 + 8) * CH + cc) =
                make_float2(acc[mt][nt][2] + b0, acc[mt][nt][3] + b1);
        }
    }
}

// ---------------------------------------------------------------------------
// Local attention: one block = 14x14 pixel tile, one (n, head).
// Halo 20x20 of K,V (+bconst) staged in smem; zero-pad neighbors = bconst only.
// float4 everywhere; row stride 36 floats -> 16B aligned, conflict-free.
// ---------------------------------------------------------------------------
__global__ void attn_kernel() {
    extern __shared__ float sm[];
    float* Ks = sm;                     // HALOSZ * ROWP
    float* Vs = sm + HALOSZ * ROWP;

    int tx0 = blockIdx.x * TILE;
    int ty0 = blockIdx.y * TILE;
    int h = blockIdx.z & 7;
    int n = blockIdx.z >> 3;
    int tid = threadIdx.x;
    int cbase = h * DIM;

    const float* Kp = g_Kp + (size_t)n * PPIX * CH;
    const float* Vp = g_Vp + (size_t)n * PPIX * CH;

    // fill halo: HALOSZ*8 float4 per matrix
    for (int idx = tid; idx < HALOSZ * 8; idx += blockDim.x) {
        int hp = idx >> 3;
        int c4 = (idx & 7) * 4;
        int gy = ty0 - 3 + hp / HALO;
        int gx = tx0 - 3 + hp % HALO;
        float4 kv = *reinterpret_cast<const float4*>(g_bck + cbase + c4);
        float4 vv = *reinterpret_cast<const float4*>(g_bcv + cbase + c4);
        if (gy >= 0 && gy < 56 && gx >= 0 && gx < 56) {
            size_t gp = (size_t)(gy * 56 + gx) * CH + cbase + c4;
            float4 k4 = *reinterpret_cast<const float4*>(Kp + gp);
            float4 v4 = *reinterpret_cast<const float4*>(Vp + gp);
            kv.x += k4.x; kv.y += k4.y; kv.z += k4.z; kv.w += k4.w;
            vv.x += v4.x; vv.y += v4.y; vv.z += v4.z; vv.w += v4.w;
        }
        *reinterpret_cast<float4*>(Ks + hp * ROWP + c4) = kv;
        *reinterpret_cast<float4*>(Vs + hp * ROWP + c4) = vv;
    }
    __syncthreads();

    if (tid >= TILE * TILE) return;
    int ly = tid / TILE, lx = tid % TILE;
    int p = (ty0 + ly) * 56 + (tx0 + lx);

    float4 q4[8];
    const float* qptr = g_Qp + (size_t)n * PPIX * CH + (size_t)p * CH + cbase;
    #pragma unroll
    for (int i = 0; i < 8; i++)
        q4[i] = *reinterpret_cast<const float4*>(qptr + i * 4);

    const float scale = 0.17677669529663687f;   // 1/sqrt(32)
    float sc[K2];
    #pragma unroll
    for (int ti = 0; ti < KER; ti++) {
        #pragma unroll
        for (int tj = 0; tj < KER; tj++) {
            const float4* kr = reinterpret_cast<const float4*>(
                Ks + ((ly + ti) * HALO + (lx + tj)) * ROWP);
            float s = 0.f;
            #pragma unroll
            for (int c = 0; c < 8; c++) {
                float4 k4 = kr[c];
                s += q4[c].x * k4.x + q4[c].y * k4.y + q4[c].z * k4.z + q4[c].w * k4.w;
            }
            sc[ti * KER + tj] = s * scale;
        }
    }

    float mx = sc[0];
    #pragma unroll
    for (int t = 1; t < K2; t++) mx = fmaxf(mx, sc[t]);
    float sum = 0.f;
    #pragma unroll
    for (int t = 0; t < K2; t++) { sc[t] = __expf(sc[t] - mx); sum += sc[t]; }
    float inv = 1.f / sum;

    float4 o4[8];
    #pragma unroll
    for (int c = 0; c < 8; c++) o4[c] = make_float4(0.f, 0.f, 0.f, 0.f);
    #pragma unroll
    for (int ti = 0; ti < KER; ti++) {
        #pragma unroll
        for (int tj = 0; tj < KER; tj++) {
            const float4* vr = reinterpret_cast<const float4*>(
                Vs + ((ly + ti) * HALO + (lx + tj)) * ROWP);
            float wgt = sc[ti * KER + tj] * inv;
            #pragma unroll
            for (int c = 0; c < 8; c++) {
                float4 v4 = vr[c];
                o4[c].x += wgt * v4.x; o4[c].y += wgt * v4.y;
                o4[c].z += wgt * v4.z; o4[c].w += wgt * v4.w;
            }
        }
    }

    float* optr = g_O + (size_t)n * PPIX * CH + (size_t)p * CH + cbase;
    #pragma unroll
    for (int i = 0; i < 8; i++)
        *reinterpret_cast<float4*>(optr + i * 4) = o4[i];
}

// ---------------------------------------------------------------------------
// Out projection (tf32 tensor cores):
//   out[n][c'][p] = sum_c O[n][p][c] * Wout[c'][c] + bout[c']
// ---------------------------------------------------------------------------
__global__ void outproj_gemm(const float* __restrict__ Wout, const float* __restrict__ bout,
                             float* __restrict__ out) {
    int nb = blockIdx.z;
    const float* A = g_O + (size_t)nb * PPIX * CH;

    __shared__ uint32_t As[16][72];
    __shared__ uint32_t Bs[16][136];

    int tid = threadIdx.x;
    int m0 = blockIdx.x * 64;
    int c0 = blockIdx.y * 128;
    int w = tid >> 5, lane = tid & 31;
    int r = lane >> 2, tig = lane & 3;
    int wm = (w & 1) * 32;
    int wn = (w >> 1) * 32;

    float acc[2][4][4];
    #pragma unroll
    for (int mt = 0; mt < 2; mt++)
        #pragma unroll
        for (int nt = 0; nt < 4; nt++)
            #pragma unroll
            for (int i = 0; i < 4; i++) acc[mt][nt][i] = 0.f;

    int a_m = tid >> 2;            // 0..63
    int a_kk = (tid & 3) * 4;      // 0..12
    int b_n = tid >> 2;
    int b_k = (tid & 3) * 4;

    for (int kt = 0; kt < CH; kt += 16) {
        // A tile: O[m][k] row-major -> transpose into k-major smem
        float4 va = *reinterpret_cast<const float4*>(A + (size_t)(m0 + a_m) * CH + kt + a_kk);
        As[a_kk + 0][a_m] = f2tf(va.x);
        As[a_kk + 1][a_m] = f2tf(va.y);
        As[a_kk + 2][a_m] = f2tf(va.z);
        As[a_kk + 3][a_m] = f2tf(va.w);
        #pragma unroll
        for (int ph = 0; ph < 2; ph++) {
            int nn = ph * 64 + b_n;
            float4 vb = *reinterpret_cast<const float4*>(Wout + (size_t)(c0 + nn) * CH + kt + b_k);
            Bs[b_k + 0][nn] = f2tf(vb.x);
            Bs[b_k + 1][nn] = f2tf(vb.y);
            Bs[b_k + 2][nn] = f2tf(vb.z);
            Bs[b_k + 3][nn] = f2tf(vb.w);
        }
        __syncthreads();

        #pragma unroll
        for (int ks = 0; ks < 2; ks++) {
            int k0 = ks * 8;
            uint32_t a[2][4], b[4][2];
            #pragma unroll
            for (int mt = 0; mt < 2; mt++) {
                int m = wm + mt * 16 + r;
                a[mt][0] = As[k0 + tig][m];
                a[mt][1] = As[k0 + tig][m + 8];
                a[mt][2] = As[k0 + tig + 4][m];
                a[mt][3] = As[k0 + tig + 4][m + 8];
            }
            #pragma unroll
            for (int nt = 0; nt < 4; nt++) {
                int nn = wn + nt * 8 + r;
                b[nt][0] = Bs[k0 + tig][nn];
                b[nt][1] = Bs[k0 + tig + 4][nn];
            }
            #pragma unroll
            for (int mt = 0; mt < 2; mt++)
                #pragma unroll
                for (int nt = 0; nt < 4; nt++)
                    mma_tf32(acc[mt][nt], a[mt], b[nt]);
        }
        __syncthreads();
    }

    // epilogue: transposed store out[c'][p]
    float* ob = out + (size_t)nb * CH * PPIX;
    #pragma unroll
    for (int mt = 0; mt < 2; mt++) {
        int row0 = m0 + wm + mt * 16 + r;
        #pragma unroll
        for (int nt = 0; nt < 4; nt++) {
            int cc = c0 + wn + nt * 8 + 2 * tig;
            float b0 = bout[cc], b1 = bout[cc + 1];
            ob[(size_t)cc * PPIX + row0]           = acc[mt][nt][0] + b0;
            ob[(size_t)(cc + 1) * PPIX + row0]     = acc[mt][nt][1] + b1;
            ob[(size_t)cc * PPIX + row0 + 8]       = acc[mt][nt][2] + b0;
            ob[(size_t)(cc + 1) * PPIX + row0 + 8] = acc[mt][nt][3] + b1;
        }
    }
}

extern "C" void kernel_launch(void* const* d_in, const int* in_sizes, int n_in,
                              void* d_out, int out_size) {
    const float* queries = (const float*)d_in[0];
    const float* key     = (const float*)d_in[1];
    const float* pos     = (const float*)d_in[2];
    const float* ipw     = (const float*)d_in[3];
    const float* ipb     = (const float*)d_in[4];
    const float* opw     = (const float*)d_in[5];
    const float* opb     = (const float*)d_in[6];
    float* out = (float*)d_out;

    bconst_kernel<<<1, 256>>>(ipw, ipb, pos);
    proj_gemm<<<dim3(49, 2, 6), 256>>>(queries, key, ipw, ipb);

    int smem = 2 * HALOSZ * ROWP * (int)sizeof(float);   // 115200 B
    cudaFuncSetAttribute(attn_kernel, cudaFuncAttributeMaxDynamicSharedMemorySize, smem);
    attn_kernel<<<dim3(4, 4, 16), 256, smem>>>();

    outproj_gemm<<<dim3(49, 2, 2), 256>>>(opw, opb, out);
}

// round 3
// speedup vs baseline: 3.0512x; 1.9500x over previous
#include <cuda_runtime.h>
#include <cstdint>

#define PPIX 3136
#define CH 256
#define DIM 32
#define KER 7
#define K2 49
#define TILE 14
#define HALO 20
#define HALOSZ 400
#define ROWP 36

// scratch (allocation-free rule: device globals)
__device__ __align__(16) float g_Qp[2 * PPIX * CH];
__device__ __align__(16) float g_Kp[2 * PPIX * CH];
__device__ __align__(16) float g_Vp[2 * PPIX * CH];
__device__ __align__(16) float g_O [2 * PPIX * CH];
__device__ __align__(16) float g_bck[CH];
__device__ __align__(16) float g_bcv[CH];

// ---------------------------------------------------------------------------
// helpers
// ---------------------------------------------------------------------------
__device__ __forceinline__ uint32_t f2tf(float x) {
    uint32_t r;
    asm("cvt.rna.tf32.f32 %0, %1;" : "=r"(r) : "f"(x));
    return r;
}
__device__ __forceinline__ uint4 cvt4(float4 v) {
    uint4 u;
    u.x = f2tf(v.x); u.y = f2tf(v.y); u.z = f2tf(v.z); u.w = f2tf(v.w);
    return u;
}
__device__ __forceinline__ void mma_tf32(float c[4], const uint32_t a[4], const uint32_t b[2]) {
    asm volatile(
        "mma.sync.aligned.m16n8k8.row.col.f32.tf32.tf32.f32 "
        "{%0,%1,%2,%3}, {%4,%5,%6,%7}, {%8,%9}, {%0,%1,%2,%3};"
        : "+f"(c[0]), "+f"(c[1]), "+f"(c[2]), "+f"(c[3])
        : "r"(a[0]), "r"(a[1]), "r"(a[2]), "r"(a[3]), "r"(b[0]), "r"(b[1]));
}

// ---------------------------------------------------------------------------
// bconst[c'] = pos * sum_c W[c'][c] + b[c']   (K and V blocks of in_proj)
// warp per channel, shuffle reduce.  grid 32 x 256 threads = 256 warps.
// ---------------------------------------------------------------------------
__global__ void bconst_kernel(const float* __restrict__ W, const float* __restrict__ b,
                              const float* __restrict__ pos) {
    int c = blockIdx.x * 8 + (threadIdx.x >> 5);
    int lane = threadIdx.x & 31;
    float p = pos[0];
    const float4* wk = reinterpret_cast<const float4*>(W + (size_t)(CH + c) * CH);
    const float4* wv = reinterpret_cast<const float4*>(W + (size_t)(2 * CH + c) * CH);
    float4 a0 = wk[lane * 2], a1 = wk[lane * 2 + 1];
    float4 v0 = wv[lane * 2], v1 = wv[lane * 2 + 1];
    float sk = a0.x + a0.y + a0.z + a0.w + a1.x + a1.y + a1.z + a1.w;
    float sv = v0.x + v0.y + v0.z + v0.w + v1.x + v1.y + v1.z + v1.w;
    #pragma unroll
    for (int o = 16; o > 0; o >>= 1) {
        sk += __shfl_xor_sync(0xffffffffu, sk, o);
        sv += __shfl_xor_sync(0xffffffffu, sv, o);
    }
    if (lane == 0) {
        g_bck[c] = p * sk + b[CH + c];
        g_bcv[c] = p * sv + b[2 * CH + c];
    }
}

// ---------------------------------------------------------------------------
// Projection GEMM (tf32, BM=64 BN=128 BK=32, double-buffered):
//   Out[p][c'] = sum_c W[c'][c] * In[c][p]  (+ bias for Q only)
// In is channel-major (C,P) -> A smem k-major [32][72].
// W row-major (n,k)         -> B smem n-major [128][36].
// 8 warps 2m x 4n, warp tile 32x32, mma m16n8k8.  blockIdx.z = proj*2 + n
// ---------------------------------------------------------------------------
__global__ void __launch_bounds__(256, 2)
proj_gemm(const float* __restrict__ queries, const float* __restrict__ key,
          const float* __restrict__ Wall, const float* __restrict__ bvec) {
    int proj = blockIdx.z >> 1;
    int n    = blockIdx.z & 1;
    const float* In = ((proj == 0) ? queries : key) + (size_t)n * CH * PPIX;
    const float* W  = Wall + (size_t)proj * CH * CH;
    float* Out = (proj == 0 ? g_Qp : (proj == 1 ? g_Kp : g_Vp)) + (size_t)n * PPIX * CH;

    extern __shared__ uint32_t sm[];
    uint32_t* As = sm;                 // [2][32][72]
    uint32_t* Bs = sm + 2 * 2304;      // [2][128][36]

    int tid = threadIdx.x;
    int m0 = blockIdx.x * 64;
    int c0 = blockIdx.y * 128;
    int w = tid >> 5, lane = tid & 31;
    int r = lane >> 2, tig = lane & 3;
    int wm = (w & 1) * 32;
    int wn = (w >> 1) * 32;

    int a_k  = tid >> 4;            // 0..15 (+16 for second chunk)
    int a_m4 = (tid & 15) * 4;
    int b_n  = tid >> 3;            // 0..31 (+32*i)
    int b_k4 = (tid & 7) * 4;

    float acc[2][4][4] = {};
    float4 sa[2], sb[4];

    auto load_tile = [&](int kt) {
        sa[0] = *reinterpret_cast<const float4*>(In + (size_t)(kt + a_k)      * PPIX + m0 + a_m4);
        sa[1] = *reinterpret_cast<const float4*>(In + (size_t)(kt + a_k + 16) * PPIX + m0 + a_m4);
        #pragma unroll
        for (int i = 0; i < 4; i++)
            sb[i] = *reinterpret_cast<const float4*>(W + (size_t)(c0 + b_n + i * 32) * CH + kt + b_k4);
    };
    auto store_tile = [&](int buf) {
        uint32_t* Ab = As + buf * 2304;
        uint32_t* Bb = Bs + buf * 4608;
        *reinterpret_cast<uint4*>(Ab + a_k * 72 + a_m4)        = cvt4(sa[0]);
        *reinterpret_cast<uint4*>(Ab + (a_k + 16) * 72 + a_m4) = cvt4(sa[1]);
        #pragma unroll
        for (int i = 0; i < 4; i++)
            *reinterpret_cast<uint4*>(Bb + (b_n + i * 32) * 36 + b_k4) = cvt4(sb[i]);
    };

    load_tile(0);
    store_tile(0);
    __syncthreads();

    int buf = 0;
    for (int it = 0; it < 8; it++) {
        if (it < 7) load_tile((it + 1) * 32);
        const uint32_t* Ab = As + buf * 2304;
        const uint32_t* Bb = Bs + buf * 4608;
        #pragma unroll
        for (int ks = 0; ks < 4; ks++) {
            int k0 = ks * 8;
            uint32_t a[2][4], b[4][2];
            #pragma unroll
            for (int mt = 0; mt < 2; mt++) {
                int m = wm + mt * 16 + r;
                a[mt][0] = Ab[(k0 + tig) * 72 + m];
                a[mt][1] = Ab[(k0 + tig) * 72 + m + 8];
                a[mt][2] = Ab[(k0 + tig + 4) * 72 + m];
                a[mt][3] = Ab[(k0 + tig + 4) * 72 + m + 8];
            }
            #pragma unroll
            for (int nt = 0; nt < 4; nt++) {
                int nn = wn + nt * 8 + r;
                b[nt][0] = Bb[nn * 36 + k0 + tig];
                b[nt][1] = Bb[nn * 36 + k0 + tig + 4];
            }
            #pragma unroll
            for (int mt = 0; mt < 2; mt++)
                #pragma unroll
                for (int nt = 0; nt < 4; nt++)
                    mma_tf32(acc[mt][nt], a[mt], b[nt]);
        }
        if (it < 7) {
            store_tile(buf ^ 1);
            __syncthreads();
            buf ^= 1;
        }
    }

    #pragma unroll
    for (int mt = 0; mt < 2; mt++) {
        int row0 = m0 + wm + mt * 16 + r;
        #pragma unroll
        for (int nt = 0; nt < 4; nt++) {
            int cc = c0 + wn + nt * 8 + 2 * tig;
            float b0 = (proj == 0) ? bvec[cc] : 0.f;
            float b1 = (proj == 0) ? bvec[cc + 1] : 0.f;
            *reinterpret_cast<float2*>(Out + (size_t)row0 * CH + cc) =
                make_float2(acc[mt][nt][0] + b0, acc[mt][nt][1] + b1);
            *reinterpret_cast<float2*>(Out + (size_t)(row0 + 8) * CH + cc) =
                make_float2(acc[mt][nt][2] + b0, acc[mt][nt][3] + b1);
        }
    }
}

// ---------------------------------------------------------------------------
// Local attention, phase-split smem (K then V in the SAME 57.6KB buffer),
// 2 blocks/SM.  One block = 14x14 pixels, one (n, head).
// ---------------------------------------------------------------------------
__global__ void __launch_bounds__(256, 2) attn_kernel() {
    extern __shared__ float smf[];     // HALOSZ * ROWP floats

    int tx0 = blockIdx.x * TILE;
    int ty0 = blockIdx.y * TILE;
    int h = blockIdx.z & 7;
    int n = blockIdx.z >> 3;
    int tid = threadIdx.x;
    int cbase = h * DIM;

    const float* Kp = g_Kp + (size_t)n * PPIX * CH;
    const float* Vp = g_Vp + (size_t)n * PPIX * CH;

    int ly = tid / TILE, lx = tid % TILE;
    bool active = tid < TILE * TILE;
    int p = (ty0 + ly) * 56 + (tx0 + lx);

    // q in registers (overlaps with K fill)
    float4 q4[8];
    if (active) {
        const float* qptr = g_Qp + (size_t)n * PPIX * CH + (size_t)p * CH + cbase;
        #pragma unroll
        for (int i = 0; i < 8; i++)
            q4[i] = *reinterpret_cast<const float4*>(qptr + i * 4);
    }

    // ---- phase 1: K halo fill ----
    for (int idx = tid; idx < HALOSZ * 8; idx += 256) {
        int hp = idx >> 3;
        int c4 = (idx & 7) * 4;
        int gy = ty0 - 3 + hp / HALO;
        int gx = tx0 - 3 + hp % HALO;
        float4 kv = *reinterpret_cast<const float4*>(g_bck + cbase + c4);
        if (gy >= 0 && gy < 56 && gx >= 0 && gx < 56) {
            float4 k4 = *reinterpret_cast<const float4*>(Kp + (size_t)(gy * 56 + gx) * CH + cbase + c4);
            kv.x += k4.x; kv.y += k4.y; kv.z += k4.z; kv.w += k4.w;
        }
        *reinterpret_cast<float4*>(smf + hp * ROWP + c4) = kv;
    }
    __syncthreads();

    float sc[K2];
    if (active) {
        const float scale = 0.17677669529663687f;   // 1/sqrt(32)
        #pragma unroll
        for (int ti = 0; ti < KER; ti++) {
            #pragma unroll
            for (int tj = 0; tj < KER; tj++) {
                const float4* kr = reinterpret_cast<const float4*>(
                    smf + ((ly + ti) * HALO + (lx + tj)) * ROWP);
                float s = 0.f;
                #pragma unroll
                for (int c = 0; c < 8; c++) {
                    float4 k4 = kr[c];
                    s += q4[c].x * k4.x + q4[c].y * k4.y + q4[c].z * k4.z + q4[c].w * k4.w;
                }
                sc[ti * KER + tj] = s * scale;
            }
        }
        float mx = sc[0];
        #pragma unroll
        for (int t = 1; t < K2; t++) mx = fmaxf(mx, sc[t]);
        float sum = 0.f;
        #pragma unroll
        for (int t = 0; t < K2; t++) { sc[t] = __expf(sc[t] - mx); sum += sc[t]; }
        float inv = 1.f / sum;
        #pragma unroll
        for (int t = 0; t < K2; t++) sc[t] *= inv;
    }
    __syncthreads();   // everyone done reading K before V overwrites

    // ---- phase 2: V halo fill (same buffer) ----
    for (int idx = tid; idx < HALOSZ * 8; idx += 256) {
        int hp = idx >> 3;
        int c4 = (idx & 7) * 4;
        int gy = ty0 - 3 + hp / HALO;
        int gx = tx0 - 3 + hp % HALO;
        float4 vv = *reinterpret_cast<const float4*>(g_bcv + cbase + c4);
        if (gy >= 0 && gy < 56 && gx >= 0 && gx < 56) {
            float4 v4 = *reinterpret_cast<const float4*>(Vp + (size_t)(gy * 56 + gx) * CH + cbase + c4);
            vv.x += v4.x; vv.y += v4.y; vv.z += v4.z; vv.w += v4.w;
        }
        *reinterpret_cast<float4*>(smf + hp * ROWP + c4) = vv;
    }
    __syncthreads();

    if (active) {
        float4 o4[8];
        #pragma unroll
        for (int c = 0; c < 8; c++) o4[c] = make_float4(0.f, 0.f, 0.f, 0.f);
        #pragma unroll
        for (int ti = 0; ti < KER; ti++) {
            #pragma unroll
            for (int tj = 0; tj < KER; tj++) {
                const float4* vr = reinterpret_cast<const float4*>(
                    smf + ((ly + ti) * HALO + (lx + tj)) * ROWP);
                float wgt = sc[ti * KER + tj];
                #pragma unroll
                for (int c = 0; c < 8; c++) {
                    float4 v4 = vr[c];
                    o4[c].x += wgt * v4.x; o4[c].y += wgt * v4.y;
                    o4[c].z += wgt * v4.z; o4[c].w += wgt * v4.w;
                }
            }
        }
        float* optr = g_O + (size_t)n * PPIX * CH + (size_t)p * CH + cbase;
        #pragma unroll
        for (int i = 0; i < 8; i++)
            *reinterpret_cast<float4*>(optr + i * 4) = o4[i];
    }
}

// ---------------------------------------------------------------------------
// Out projection (tf32, double-buffered):
//   out[n][c'][p] = sum_c O[n][p][c] * Wout[c'][c] + bout[c']
// O row-major (m,k) -> A smem m-major [64][36].  B as in proj_gemm.
// ---------------------------------------------------------------------------
__global__ void __launch_bounds__(256, 2)
outproj_gemm(const float* __restrict__ Wout, const float* __restrict__ bout,
             float* __restrict__ out) {
    int nb = blockIdx.z;
    const float* A = g_O + (size_t)nb * PPIX * CH;

    extern __shared__ uint32_t sm[];
    uint32_t* As = sm;                 // [2][64][36]
    uint32_t* Bs = sm + 2 * 2304;      // [2][128][36]

    int tid = threadIdx.x;
    int m0 = blockIdx.x * 64;
    int c0 = blockIdx.y * 128;
    int w = tid >> 5, lane = tid & 31;
    int r = lane >> 2, tig = lane & 3;
    int wm = (w & 1) * 32;
    int wn = (w >> 1) * 32;

    int a_m  = tid >> 3;            // 0..31 (+32 for second chunk)
    int a_k4 = (tid & 7) * 4;
    int b_n  = tid >> 3;
    int b_k4 = (tid & 7) * 4;

    float acc[2][4][4] = {};
    float4 sa[2], sb[4];

    auto load_tile = [&](int kt) {
        sa[0] = *reinterpret_cast<const float4*>(A + (size_t)(m0 + a_m)      * CH + kt + a_k4);
        sa[1] = *reinterpret_cast<const float4*>(A + (size_t)(m0 + a_m + 32) * CH + kt + a_k4);
        #pragma unroll
        for (int i = 0; i < 4; i++)
            sb[i] = *reinterpret_cast<const float4*>(Wout + (size_t)(c0 + b_n + i * 32) * CH + kt + b_k4);
    };
    auto store_tile = [&](int buf) {
        uint32_t* Ab = As + buf * 2304;
        uint32_t* Bb = Bs + buf * 4608;
        *reinterpret_cast<uint4*>(Ab + a_m * 36 + a_k4)        = cvt4(sa[0]);
        *reinterpret_cast<uint4*>(Ab + (a_m + 32) * 36 + a_k4) = cvt4(sa[1]);
        #pragma unroll
        for (int i = 0; i < 4; i++)
            *reinterpret_cast<uint4*>(Bb + (b_n + i * 32) * 36 + b_k4) = cvt4(sb[i]);
    };

    load_tile(0);
    store_tile(0);
    __syncthreads();

    int buf = 0;
    for (int it = 0; it < 8; it++) {
        if (it < 7) load_tile((it + 1) * 32);
        const uint32_t* Ab = As + buf * 2304;
        const uint32_t* Bb = Bs + buf * 4608;
        #pragma unroll
        for (int ks = 0; ks < 4; ks++) {
            int k0 = ks * 8;
            uint32_t a[2][4], b[4][2];
            #pragma unroll
            for (int mt = 0; mt < 2; mt++) {
                int m = wm + mt * 16 + r;
                a[mt][0] = Ab[m * 36 + k0 + tig];
                a[mt][1] = Ab[(m + 8) * 36 + k0 + tig];
                a[mt][2] = Ab[m * 36 + k0 + tig + 4];
                a[mt][3] = Ab[(m + 8) * 36 + k0 + tig + 4];
            }
            #pragma unroll
            for (int nt = 0; nt < 4; nt++) {
                int nn = wn + nt * 8 + r;
                b[nt][0] = Bb[nn * 36 + k0 + tig];
                b[nt][1] = Bb[nn * 36 + k0 + tig + 4];
            }
            #pragma unroll
            for (int mt = 0; mt < 2; mt++)
                #pragma unroll
                for (int nt = 0; nt < 4; nt++)
                    mma_tf32(acc[mt][nt], a[mt], b[nt]);
        }
        if (it < 7) {
            store_tile(buf ^ 1);
            __syncthreads();
            buf ^= 1;
        }
    }

    // epilogue: transposed store out[c'][p]
    float* ob = out + (size_t)nb * CH * PPIX;
    #pragma unroll
    for (int mt = 0; mt < 2; mt++) {
        int row0 = m0 + wm + mt * 16 + r;
        #pragma unroll
        for (int nt = 0; nt < 4; nt++) {
            int cc = c0 + wn + nt * 8 + 2 * tig;
            float b0 = bout[cc], b1 = bout[cc + 1];
            ob[(size_t)cc * PPIX + row0]           = acc[mt][nt][0] + b0;
            ob[(size_t)(cc + 1) * PPIX + row0]     = acc[mt][nt][1] + b1;
            ob[(size_t)cc * PPIX + row0 + 8]       = acc[mt][nt][2] + b0;
            ob[(size_t)(cc + 1) * PPIX + row0 + 8] = acc[mt][nt][3] + b1;
        }
    }
}

extern "C" void kernel_launch(void* const* d_in, const int* in_sizes, int n_in,
                              void* d_out, int out_size) {
    const float* queries = (const float*)d_in[0];
    const float* key     = (const float*)d_in[1];
    const float* pos     = (const float*)d_in[2];
    const float* ipw     = (const float*)d_in[3];
    const float* ipb     = (const float*)d_in[4];
    const float* opw     = (const float*)d_in[5];
    const float* opb     = (const float*)d_in[6];
    float* out = (float*)d_out;

    const int gemm_smem = (2 * 2304 + 2 * 4608) * (int)sizeof(uint32_t);   // 55296
    const int attn_smem = HALOSZ * ROWP * (int)sizeof(float);              // 57600

    cudaFuncSetAttribute(proj_gemm,    cudaFuncAttributeMaxDynamicSharedMemorySize, gemm_smem);
    cudaFuncSetAttribute(outproj_gemm, cudaFuncAttributeMaxDynamicSharedMemorySize, gemm_smem);
    cudaFuncSetAttribute(attn_kernel,  cudaFuncAttributeMaxDynamicSharedMemorySize, attn_smem);

    bconst_kernel<<<32, 256>>>(ipw, ipb, pos);
    proj_gemm<<<dim3(49, 2, 6), 256, gemm_smem>>>(queries, key, ipw, ipb);
    attn_kernel<<<dim3(4, 4, 16), 256, attn_smem>>>();
    outproj_gemm<<<dim3(49, 2, 2), 256, gemm_smem>>>(opw, opb, out);
}

// round 4
// speedup vs baseline: 3.1971x; 1.0478x over previous
#include <cuda_runtime.h>
#include <cstdint>

#define PPIX 3136
#define CH 256
#define DIM 32
#define KER 7
#define K2 49
#define TILE 14
#define HALO 20
#define HALOSZ 400
#define ROWP 36

// scratch (allocation-free rule: device globals)
__device__ __align__(16) float g_Qp[2 * PPIX * CH];
__device__ __align__(16) float g_Kp[2 * PPIX * CH];
__device__ __align__(16) float g_Vp[2 * PPIX * CH];
__device__ __align__(16) float g_O [2 * PPIX * CH];
__device__ __align__(16) float g_bck[CH];
__device__ __align__(16) float g_bcv[CH];

// ---------------------------------------------------------------------------
// helpers
// ---------------------------------------------------------------------------
__device__ __forceinline__ uint32_t f2tf(float x) {
    uint32_t r;
    asm("cvt.rna.tf32.f32 %0, %1;" : "=r"(r) : "f"(x));
    return r;
}
__device__ __forceinline__ uint4 cvt4(float4 v) {
    uint4 u;
    u.x = f2tf(v.x); u.y = f2tf(v.y); u.z = f2tf(v.z); u.w = f2tf(v.w);
    return u;
}
__device__ __forceinline__ void mma_tf32(float c[4], const uint32_t a[4], const uint32_t b[2]) {
    asm volatile(
        "mma.sync.aligned.m16n8k8.row.col.f32.tf32.tf32.f32 "
        "{%0,%1,%2,%3}, {%4,%5,%6,%7}, {%8,%9}, {%0,%1,%2,%3};"
        : "+f"(c[0]), "+f"(c[1]), "+f"(c[2]), "+f"(c[3])
        : "r"(a[0]), "r"(a[1]), "r"(a[2]), "r"(a[3]), "r"(b[0]), "r"(b[1]));
}

// ---------------------------------------------------------------------------
// bconst[c'] = pos * sum_c W[c'][c] + b[c']   (K and V blocks of in_proj)
// ---------------------------------------------------------------------------
__global__ void bconst_kernel(const float* __restrict__ W, const float* __restrict__ b,
                              const float* __restrict__ pos) {
    int c = blockIdx.x * 8 + (threadIdx.x >> 5);
    int lane = threadIdx.x & 31;
    float p = pos[0];
    const float4* wk = reinterpret_cast<const float4*>(W + (size_t)(CH + c) * CH);
    const float4* wv = reinterpret_cast<const float4*>(W + (size_t)(2 * CH + c) * CH);
    float4 a0 = wk[lane * 2], a1 = wk[lane * 2 + 1];
    float4 v0 = wv[lane * 2], v1 = wv[lane * 2 + 1];
    float sk = a0.x + a0.y + a0.z + a0.w + a1.x + a1.y + a1.z + a1.w;
    float sv = v0.x + v0.y + v0.z + v0.w + v1.x + v1.y + v1.z + v1.w;
    #pragma unroll
    for (int o = 16; o > 0; o >>= 1) {
        sk += __shfl_xor_sync(0xffffffffu, sk, o);
        sv += __shfl_xor_sync(0xffffffffu, sv, o);
    }
    if (lane == 0) {
        g_bck[c] = p * sk + b[CH + c];
        g_bcv[c] = p * sv + b[2 * CH + c];
    }
}

// ---------------------------------------------------------------------------
// Projection GEMM (tf32, BM=64 BN=128 BK=32, double-buffered, 128 threads):
//   Out[p][c'] = sum_c W[c'][c] * In[c][p]  (+ bias for Q only)
// 4 warps 2m x 2n, warp tile 32x64 (mt=2, nt=8).  3 CTAs/SM.
// In channel-major (C,P) -> A smem k-major [32][72].
// W row-major (n,k)      -> B smem n-major [128][36].
// blockIdx.z = proj*2 + n
// ---------------------------------------------------------------------------
__global__ void __launch_bounds__(128, 3)
proj_gemm(const float* __restrict__ queries, const float* __restrict__ key,
          const float* __restrict__ Wall, const float* __restrict__ bvec) {
    int proj = blockIdx.z >> 1;
    int n    = blockIdx.z & 1;
    const float* In = ((proj == 0) ? queries : key) + (size_t)n * CH * PPIX;
    const float* W  = Wall + (size_t)proj * CH * CH;
    float* Out = (proj == 0 ? g_Qp : (proj == 1 ? g_Kp : g_Vp)) + (size_t)n * PPIX * CH;

    extern __shared__ uint32_t sm[];
    uint32_t* As = sm;                 // [2][32][72]
    uint32_t* Bs = sm + 2 * 2304;      // [2][128][36]

    int tid = threadIdx.x;
    int m0 = blockIdx.x * 64;
    int c0 = blockIdx.y * 128;
    int w = tid >> 5, lane = tid & 31;
    int r = lane >> 2, tig = lane & 3;
    int wm = (w & 1) * 32;
    int wn = (w >> 1) * 64;

    int a_k  = tid >> 4;            // 0..7 (+8*i)
    int a_m4 = (tid & 15) * 4;
    int b_n  = tid >> 3;            // 0..15 (+16*i)
    int b_k4 = (tid & 7) * 4;

    float acc[2][8][4] = {};
    float4 sa[4], sb[8];

    auto load_tile = [&](int kt) {
        #pragma unroll
        for (int i = 0; i < 4; i++)
            sa[i] = *reinterpret_cast<const float4*>(In + (size_t)(kt + a_k + 8 * i) * PPIX + m0 + a_m4);
        #pragma unroll
        for (int i = 0; i < 8; i++)
            sb[i] = *reinterpret_cast<const float4*>(W + (size_t)(c0 + b_n + 16 * i) * CH + kt + b_k4);
    };
    auto store_tile = [&](int buf) {
        uint32_t* Ab = As + buf * 2304;
        uint32_t* Bb = Bs + buf * 4608;
        #pragma unroll
        for (int i = 0; i < 4; i++)
            *reinterpret_cast<uint4*>(Ab + (a_k + 8 * i) * 72 + a_m4) = cvt4(sa[i]);
        #pragma unroll
        for (int i = 0; i < 8; i++)
            *reinterpret_cast<uint4*>(Bb + (b_n + 16 * i) * 36 + b_k4) = cvt4(sb[i]);
    };

    load_tile(0);
    store_tile(0);
    __syncthreads();

    int buf = 0;
    for (int it = 0; it < 8; it++) {
        if (it < 7) load_tile((it + 1) * 32);
        const uint32_t* Ab = As + buf * 2304;
        const uint32_t* Bb = Bs + buf * 4608;
        #pragma unroll
        for (int ks = 0; ks < 4; ks++) {
            int k0 = ks * 8;
            uint32_t a[2][4], b[8][2];
            #pragma unroll
            for (int mt = 0; mt < 2; mt++) {
                int m = wm + mt * 16 + r;
                a[mt][0] = Ab[(k0 + tig) * 72 + m];
                a[mt][1] = Ab[(k0 + tig) * 72 + m + 8];
                a[mt][2] = Ab[(k0 + tig + 4) * 72 + m];
                a[mt][3] = Ab[(k0 + tig + 4) * 72 + m + 8];
            }
            #pragma unroll
            for (int nt = 0; nt < 8; nt++) {
                int nn = wn + nt * 8 + r;
                b[nt][0] = Bb[nn * 36 + k0 + tig];
                b[nt][1] = Bb[nn * 36 + k0 + tig + 4];
            }
            #pragma unroll
            for (int mt = 0; mt < 2; mt++)
                #pragma unroll
                for (int nt = 0; nt < 8; nt++)
                    mma_tf32(acc[mt][nt], a[mt], b[nt]);
        }
        if (it < 7) {
            store_tile(buf ^ 1);
            __syncthreads();
            buf ^= 1;
        }
    }

    #pragma unroll
    for (int mt = 0; mt < 2; mt++) {
        int row0 = m0 + wm + mt * 16 + r;
        #pragma unroll
        for (int nt = 0; nt < 8; nt++) {
            int cc = c0 + wn + nt * 8 + 2 * tig;
            float b0 = (proj == 0) ? bvec[cc] : 0.f;
            float b1 = (proj == 0) ? bvec[cc + 1] : 0.f;
            *reinterpret_cast<float2*>(Out + (size_t)row0 * CH + cc) =
                make_float2(acc[mt][nt][0] + b0, acc[mt][nt][1] + b1);
            *reinterpret_cast<float2*>(Out + (size_t)(row0 + 8) * CH + cc) =
                make_float2(acc[mt][nt][2] + b0, acc[mt][nt][3] + b1);
        }
    }
}

// ---------------------------------------------------------------------------
// Local attention, phase-split smem (K then V in the SAME 57.6KB buffer),
// 2 blocks/SM.  One block = 14x14 pixels, one (n, head).
// ---------------------------------------------------------------------------
__global__ void __launch_bounds__(256, 2) attn_kernel() {
    extern __shared__ float smf[];     // HALOSZ * ROWP floats

    int tx0 = blockIdx.x * TILE;
    int ty0 = blockIdx.y * TILE;
    int h = blockIdx.z & 7;
    int n = blockIdx.z >> 3;
    int tid = threadIdx.x;
    int cbase = h * DIM;

    const float* Kp = g_Kp + (size_t)n * PPIX * CH;
    const float* Vp = g_Vp + (size_t)n * PPIX * CH;

    int ly = tid / TILE, lx = tid % TILE;
    bool active = tid < TILE * TILE;
    int p = (ty0 + ly) * 56 + (tx0 + lx);

    float4 q4[8];
    if (active) {
        const float* qptr = g_Qp + (size_t)n * PPIX * CH + (size_t)p * CH + cbase;
        #pragma unroll
        for (int i = 0; i < 8; i++)
            q4[i] = *reinterpret_cast<const float4*>(qptr + i * 4);
    }

    // ---- phase 1: K halo fill ----
    for (int idx = tid; idx < HALOSZ * 8; idx += 256) {
        int hp = idx >> 3;
        int c4 = (idx & 7) * 4;
        int gy = ty0 - 3 + hp / HALO;
        int gx = tx0 - 3 + hp % HALO;
        float4 kv = *reinterpret_cast<const float4*>(g_bck + cbase + c4);
        if (gy >= 0 && gy < 56 && gx >= 0 && gx < 56) {
            float4 k4 = *reinterpret_cast<const float4*>(Kp + (size_t)(gy * 56 + gx) * CH + cbase + c4);
            kv.x += k4.x; kv.y += k4.y; kv.z += k4.z; kv.w += k4.w;
        }
        *reinterpret_cast<float4*>(smf + hp * ROWP + c4) = kv;
    }
    __syncthreads();

    float sc[K2];
    if (active) {
        const float scale = 0.17677669529663687f;   // 1/sqrt(32)
        #pragma unroll
        for (int ti = 0; ti < KER; ti++) {
            #pragma unroll
            for (int tj = 0; tj < KER; tj++) {
                const float4* kr = reinterpret_cast<const float4*>(
                    smf + ((ly + ti) * HALO + (lx + tj)) * ROWP);
                float s = 0.f;
                #pragma unroll
                for (int c = 0; c < 8; c++) {
                    float4 k4 = kr[c];
                    s += q4[c].x * k4.x + q4[c].y * k4.y + q4[c].z * k4.z + q4[c].w * k4.w;
                }
                sc[ti * KER + tj] = s * scale;
            }
        }
        float mx = sc[0];
        #pragma unroll
        for (int t = 1; t < K2; t++) mx = fmaxf(mx, sc[t]);
        float sum = 0.f;
        #pragma unroll
        for (int t = 0; t < K2; t++) { sc[t] = __expf(sc[t] - mx); sum += sc[t]; }
        float inv = 1.f / sum;
        #pragma unroll
        for (int t = 0; t < K2; t++) sc[t] *= inv;
    }
    __syncthreads();

    // ---- phase 2: V halo fill (same buffer) ----
    for (int idx = tid; idx < HALOSZ * 8; idx += 256) {
        int hp = idx >> 3;
        int c4 = (idx & 7) * 4;
        int gy = ty0 - 3 + hp / HALO;
        int gx = tx0 - 3 + hp % HALO;
        float4 vv = *reinterpret_cast<const float4*>(g_bcv + cbase + c4);
        if (gy >= 0 && gy < 56 && gx >= 0 && gx < 56) {
            float4 v4 = *reinterpret_cast<const float4*>(Vp + (size_t)(gy * 56 + gx) * CH + cbase + c4);
            vv.x += v4.x; vv.y += v4.y; vv.z += v4.z; vv.w += v4.w;
        }
        *reinterpret_cast<float4*>(smf + hp * ROWP + c4) = vv;
    }
    __syncthreads();

    if (active) {
        float4 o4[8];
        #pragma unroll
        for (int c = 0; c < 8; c++) o4[c] = make_float4(0.f, 0.f, 0.f, 0.f);
        #pragma unroll
        for (int ti = 0; ti < KER; ti++) {
            #pragma unroll
            for (int tj = 0; tj < KER; tj++) {
                const float4* vr = reinterpret_cast<const float4*>(
                    smf + ((ly + ti) * HALO + (lx + tj)) * ROWP);
                float wgt = sc[ti * KER + tj];
                #pragma unroll
                for (int c = 0; c < 8; c++) {
                    float4 v4 = vr[c];
                    o4[c].x += wgt * v4.x; o4[c].y += wgt * v4.y;
                    o4[c].z += wgt * v4.z; o4[c].w += wgt * v4.w;
                }
            }
        }
        float* optr = g_O + (size_t)n * PPIX * CH + (size_t)p * CH + cbase;
        #pragma unroll
        for (int i = 0; i < 8; i++)
            *reinterpret_cast<float4*>(optr + i * 4) = o4[i];
    }
}

// ---------------------------------------------------------------------------
// Out projection (tf32, BM=64 BN=128 BK=32, double-buffered, 128 threads):
//   out[n][c'][p] = sum_c O[n][p][c] * Wout[c'][c] + bout[c']
// O row-major (m,k) -> A smem m-major [64][36].
// ---------------------------------------------------------------------------
__global__ void __launch_bounds__(128, 3)
outproj_gemm(const float* __restrict__ Wout, const float* __restrict__ bout,
             float* __restrict__ out) {
    int nb = blockIdx.z;
    const float* A = g_O + (size_t)nb * PPIX * CH;

    extern __shared__ uint32_t sm[];
    uint32_t* As = sm;                 // [2][64][36]
    uint32_t* Bs = sm + 2 * 2304;      // [2][128][36]

    int tid = threadIdx.x;
    int m0 = blockIdx.x * 64;
    int c0 = blockIdx.y * 128;
    int w = tid >> 5, lane = tid & 31;
    int r = lane >> 2, tig = lane & 3;
    int wm = (w & 1) * 32;
    int wn = (w >> 1) * 64;

    int a_m  = tid >> 3;            // 0..15 (+16*i)
    int a_k4 = (tid & 7) * 4;
    int b_n  = tid >> 3;
    int b_k4 = (tid & 7) * 4;

    float acc[2][8][4] = {};
    float4 sa[4], sb[8];

    auto load_tile = [&](int kt) {
        #pragma unroll
        for (int i = 0; i < 4; i++)
            sa[i] = *reinterpret_cast<const float4*>(A + (size_t)(m0 + a_m + 16 * i) * CH + kt + a_k4);
        #pragma unroll
        for (int i = 0; i < 8; i++)
            sb[i] = *reinterpret_cast<const float4*>(Wout + (size_t)(c0 + b_n + 16 * i) * CH + kt + b_k4);
    };
    auto store_tile = [&](int buf) {
        uint32_t* Ab = As + buf * 2304;
        uint32_t* Bb = Bs + buf * 4608;
        #pragma unroll
        for (int i = 0; i < 4; i++)
            *reinterpret_cast<uint4*>(Ab + (a_m + 16 * i) * 36 + a_k4) = cvt4(sa[i]);
        #pragma unroll
        for (int i = 0; i < 8; i++)
            *reinterpret_cast<uint4*>(Bb + (b_n + 16 * i) * 36 + b_k4) = cvt4(sb[i]);
    };

    load_tile(0);
    store_tile(0);
    __syncthreads();

    int buf = 0;
    for (int it = 0; it < 8; it++) {
        if (it < 7) load_tile((it + 1) * 32);
        const uint32_t* Ab = As + buf * 2304;
        const uint32_t* Bb = Bs + buf * 4608;
        #pragma unroll
        for (int ks = 0; ks < 4; ks++) {
            int k0 = ks * 8;
            uint32_t a[2][4], b[8][2];
            #pragma unroll
            for (int mt = 0; mt < 2; mt++) {
                int m = wm + mt * 16 + r;
                a[mt][0] = Ab[m * 36 + k0 + tig];
                a[mt][1] = Ab[(m + 8) * 36 + k0 + tig];
                a[mt][2] = Ab[m * 36 + k0 + tig + 4];
                a[mt][3] = Ab[(m + 8) * 36 + k0 + tig + 4];
            }
            #pragma unroll
            for (int nt = 0; nt < 8; nt++) {
                int nn = wn + nt * 8 + r;
                b[nt][0] = Bb[nn * 36 + k0 + tig];
                b[nt][1] = Bb[nn * 36 + k0 + tig + 4];
            }
            #pragma unroll
            for (int mt = 0; mt < 2; mt++)
                #pragma unroll
                for (int nt = 0; nt < 8; nt++)
                    mma_tf32(acc[mt][nt], a[mt], b[nt]);
        }
        if (it < 7) {
            store_tile(buf ^ 1);
            __syncthreads();
            buf ^= 1;
        }
    }

    // epilogue: transposed store out[c'][p]
    float* ob = out + (size_t)nb * CH * PPIX;
    #pragma unroll
    for (int mt = 0; mt < 2; mt++) {
        int row0 = m0 + wm + mt * 16 + r;
        #pragma unroll
        for (int nt = 0; nt < 8; nt++) {
            int cc = c0 + wn + nt * 8 + 2 * tig;
            float b0 = bout[cc], b1 = bout[cc + 1];
            ob[(size_t)cc * PPIX + row0]           = acc[mt][nt][0] + b0;
            ob[(size_t)(cc + 1) * PPIX + row0]     = acc[mt][nt][1] + b1;
            ob[(size_t)cc * PPIX + row0 + 8]       = acc[mt][nt][2] + b0;
            ob[(size_t)(cc + 1) * PPIX + row0 + 8] = acc[mt][nt][3] + b1;
        }
    }
}

extern "C" void kernel_launch(void* const* d_in, const int* in_sizes, int n_in,
                              void* d_out, int out_size) {
    const float* queries = (const float*)d_in[0];
    const float* key     = (const float*)d_in[1];
    const float* pos     = (const float*)d_in[2];
    const float* ipw     = (const float*)d_in[3];
    const float* ipb     = (const float*)d_in[4];
    const float* opw     = (const float*)d_in[5];
    const float* opb     = (const float*)d_in[6];
    float* out = (float*)d_out;

    const int gemm_smem = (2 * 2304 + 2 * 4608) * (int)sizeof(uint32_t);   // 55296
    const int attn_smem = HALOSZ * ROWP * (int)sizeof(float);              // 57600

    cudaFuncSetAttribute(proj_gemm,    cudaFuncAttributeMaxDynamicSharedMemorySize, gemm_smem);
    cudaFuncSetAttribute(outproj_gemm, cudaFuncAttributeMaxDynamicSharedMemorySize, gemm_smem);
    cudaFuncSetAttribute(attn_kernel,  cudaFuncAttributeMaxDynamicSharedMemorySize, attn_smem);

    bconst_kernel<<<32, 256>>>(ipw, ipb, pos);
    proj_gemm<<<dim3(49, 2, 6), 128, gemm_smem>>>(queries, key, ipw, ipb);
    attn_kernel<<<dim3(4, 4, 16), 256, attn_smem>>>();
    outproj_gemm<<<dim3(49, 2, 2), 128, gemm_smem>>>(opw, opb, out);
}